// round 6
// baseline (speedup 1.0000x reference)
#include <cuda_runtime.h>
#include <cuda_fp16.h>
#include <stdint.h>

// out[32768,256] = A[32768, K=2304] * Wt[K,256], fp16 operands, fp32 accum,
// ldmatrix + mma.sync.m16n8k16 (portable for compute_100).
//
// K layout: k = 9*i + j; j=0: silu(x_i), j=1..8: cubic B-spline bases
// (closed-form: only 4 nonzero, placed by select chain).
// CTA tile: 64 rows x 256 outs (full N -> A generated once, not twice).
// Chunk: 16 features = 144 k = 9 k16 steps. A gen'd on the fly; B cp.async.
// SMEM rows: 304-byte stride (76 words, 12 mod 32 -> ldmatrix conflict-free).

#define N_IN   256
#define KTOT   2304
#define CHUNKS 16
#define CK     144
#define KSTEPS 9
#define ROWB   304
#define ABUF   (64 * ROWB)            // 19456
#define BBUF   (256 * ROWB)           // 77824
#define DYN_SMEM (2 * ABUF + 2 * BBUF) // 194560

__device__ __align__(128) __half g_Wh[N_IN * KTOT];   // [out][k] fp16

// ---- helpers --------------------------------------------------------------
__device__ __forceinline__ uint32_t smem_u32(const void* p) {
    uint32_t a;
    asm("{ .reg .u64 t; cvta.to.shared.u64 t, %1; cvt.u32.u64 %0, t; }" : "=r"(a) : "l"(p));
    return a;
}
__device__ __forceinline__ void cp16(uint32_t dst, const void* src) {
    asm volatile("cp.async.cg.shared.global [%0], [%1], 16;" :: "r"(dst), "l"(src) : "memory");
}
__device__ __forceinline__ void cp_commit() {
    asm volatile("cp.async.commit_group;" ::: "memory");
}
template <int N>
__device__ __forceinline__ void cp_wait() {
    asm volatile("cp.async.wait_group %0;" :: "n"(N) : "memory");
}
__device__ __forceinline__ void ldm_x4(uint32_t& r0, uint32_t& r1, uint32_t& r2, uint32_t& r3,
                                       uint32_t addr) {
    asm volatile("ldmatrix.sync.aligned.m8n8.x4.shared.b16 {%0,%1,%2,%3}, [%4];"
                 : "=r"(r0), "=r"(r1), "=r"(r2), "=r"(r3) : "r"(addr));
}
__device__ __forceinline__ void mma16816(float& c0, float& c1, float& c2, float& c3,
                                         uint32_t a0, uint32_t a1, uint32_t a2, uint32_t a3,
                                         uint32_t b0, uint32_t b1) {
    asm volatile(
        "mma.sync.aligned.m16n8k16.row.col.f32.f16.f16.f32 "
        "{%0,%1,%2,%3}, {%4,%5,%6,%7}, {%8,%9}, {%0,%1,%2,%3};"
        : "+f"(c0), "+f"(c1), "+f"(c2), "+f"(c3)
        : "r"(a0), "r"(a1), "r"(a2), "r"(a3), "r"(b0), "r"(b1));
}

// ---- weight repack to fp16 [out][k] ---------------------------------------
__global__ void repack_kernel(const float* __restrict__ baseW,
                              const float* __restrict__ splineW) {
    int idx = blockIdx.x * blockDim.x + threadIdx.x;
    if (idx >= N_IN * KTOT) return;
    int o = idx / KTOT, k = idx % KTOT;
    int i = k / 9, j = k % 9;
    float v = (j == 0) ? baseW[o * N_IN + i] : splineW[o * (N_IN * 8) + i * 8 + (j - 1)];
    g_Wh[idx] = __float2half_rn(v);
}

// ---- main fused kernel ----------------------------------------------------
__global__ __launch_bounds__(256, 1)
void kan_hmma_kernel(const float* __restrict__ x, float* __restrict__ out) {
    extern __shared__ __align__(128) unsigned char dsm[];   // A0 A1 B0 B1
    const uint32_t sb = smem_u32(dsm);
    const int tid = threadIdx.x, wid = tid >> 5, lane = tid & 31;
    const int row0 = blockIdx.x * 64;

    // A generation: thread -> (row = tid&63, features f4*4..f4*4+3)
    const int grow = tid & 63;
    const int f4   = tid >> 6;                   // 0..3
    const float* xrow = x + (size_t)(row0 + grow) * N_IN;

    // warp tiling: 2 (m) x 4 (n); warp tile 32 rows x 64 cols
    const int wm = wid & 1;
    const int wn = wid >> 1;

    const uint32_t a_off = (uint32_t)(wm * 32 + (lane & 15)) * ROWB + ((lane >> 4) << 3) * 2;
    const uint32_t b_off = (uint32_t)(wn * 64 + ((lane >> 4) << 3) + (lane & 7)) * ROWB
                         + (((lane >> 3) & 1) << 3) * 2;

    float C[2][8][4];
#pragma unroll
    for (int a = 0; a < 2; a++)
#pragma unroll
        for (int b = 0; b < 8; b++)
#pragma unroll
            for (int c = 0; c < 4; c++) C[a][b][c] = 0.f;

    // ---- A generator: silu + closed-form cubic B-spline window ----
    auto genA = [&](int c, uint32_t abyte) {
        float4 x4 = *reinterpret_cast<const float4*>(xrow + c * 16 + f4 * 4);
        float xv[4] = {x4.x, x4.y, x4.z, x4.w};
        uint32_t pk[18];
#pragma unroll
        for (int ff = 0; ff < 4; ff++) {
            float v = xv[ff];
            float sil = v / (1.f + __expf(-v));
            // interval index and local coordinate
            int j0 = (int)floorf(fmaf(v, 2.5f, 5.5f));
            float g = fmaf(0.4f, (float)j0, -2.2f);
            float u = (v - g) * 2.5f;
            float u2 = u * u, u3 = u2 * u, omu = 1.f - u;
            float w0 = omu * omu * omu * (1.f / 6.f);
            float w1 = fmaf(0.5f, u3, fmaf(-1.f, u2, 2.f / 3.f));
            float w2 = fmaf(-0.5f, u3, fmaf(0.5f, u2, fmaf(0.5f, u, 1.f / 6.f)));
            float w3 = u3 * (1.f / 6.f);
            unsigned short h0 = __half_as_ushort(__float2half_rn(w0));
            unsigned short h1 = __half_as_ushort(__float2half_rn(w1));
            unsigned short h2 = __half_as_ushort(__float2half_rn(w2));
            unsigned short h3 = __half_as_ushort(__float2half_rn(w3));
            unsigned short hh[9];
            hh[0] = __half_as_ushort(__float2half_rn(sil));
#pragma unroll
            for (int i = 0; i < 8; i++) {
                int d = j0 - i;
                unsigned short b = (d == 0) ? h3 : (d == 1) ? h2
                                 : (d == 2) ? h1 : (d == 3) ? h0 : (unsigned short)0;
                hh[i + 1] = b;
            }
#pragma unroll
            for (int j = 0; j < 9; j++) {
                int pos = 9 * ff + j;
                uint32_t word = (uint32_t)hh[j] << ((pos & 1) * 16);
                if ((pos & 1) == 0) pk[pos >> 1] = word;
                else                pk[pos >> 1] |= word;
            }
        }
        unsigned char* dst = dsm + abyte + (uint32_t)grow * ROWB + (uint32_t)f4 * 72;
#pragma unroll
        for (int q = 0; q < 9; q++)
            *reinterpret_cast<uint2*>(dst + q * 8) = make_uint2(pk[2 * q], pk[2 * q + 1]);
    };

    // ---- B stage via cp.async: 256 rows x 18 segs of 16B ----
    auto issueB = [&](int c, uint32_t bbyte) {
        const __half* src0 = g_Wh + c * CK;
#pragma unroll
        for (int s = 0; s < 18; s++) {
            int e = tid + 256 * s;            // 0..4607
            int n = e / 18, seg = e % 18;
            cp16(sb + bbyte + (uint32_t)n * ROWB + seg * 16,
                 src0 + (size_t)n * KTOT + seg * 8);
        }
        cp_commit();
    };

    // ---- prologue ----
    genA(0, 0);
    issueB(0, 2 * ABUF);
    issueB(1, 2 * ABUF + BBUF);
    cp_wait<1>();
    __syncthreads();

    // ---- main loop ----
    for (int c = 0; c < CHUNKS; c++) {
        const int buf = c & 1;
        const uint32_t abase = sb + (uint32_t)buf * ABUF;
        const uint32_t bbase = sb + 2 * ABUF + (uint32_t)buf * BBUF;

#pragma unroll
        for (int s = 0; s < KSTEPS; s++) {
            const uint32_t kb = (uint32_t)(s * 16) * 2;
            uint32_t A[2][4], B[4][4];
#pragma unroll
            for (int mt = 0; mt < 2; mt++)
                ldm_x4(A[mt][0], A[mt][1], A[mt][2], A[mt][3],
                       abase + a_off + (uint32_t)mt * (16 * ROWB) + kb);
#pragma unroll
            for (int nt = 0; nt < 4; nt++)
                ldm_x4(B[nt][0], B[nt][1], B[nt][2], B[nt][3],
                       bbase + b_off + (uint32_t)nt * (16 * ROWB) + kb);
#pragma unroll
            for (int mt = 0; mt < 2; mt++)
#pragma unroll
                for (int nt = 0; nt < 4; nt++) {
                    mma16816(C[mt][2 * nt][0], C[mt][2 * nt][1],
                             C[mt][2 * nt][2], C[mt][2 * nt][3],
                             A[mt][0], A[mt][1], A[mt][2], A[mt][3],
                             B[nt][0], B[nt][1]);
                    mma16816(C[mt][2 * nt + 1][0], C[mt][2 * nt + 1][1],
                             C[mt][2 * nt + 1][2], C[mt][2 * nt + 1][3],
                             A[mt][0], A[mt][1], A[mt][2], A[mt][3],
                             B[nt][2], B[nt][3]);
                }
        }

        if (c + 1 < CHUNKS) genA(c + 1, (uint32_t)(buf ^ 1) * ABUF);
        __syncthreads();
        if (c + 2 < CHUNKS) {
            issueB(c + 2, 2 * ABUF + (uint32_t)buf * BBUF);
            cp_wait<1>();
        } else {
            cp_wait<0>();
        }
        __syncthreads();
    }

    // ---- epilogue ----
    const int crow = lane >> 2, ccol = (lane & 3) * 2;
#pragma unroll
    for (int mt = 0; mt < 2; mt++) {
        int r = row0 + wm * 32 + mt * 16 + crow;
#pragma unroll
        for (int nt8 = 0; nt8 < 8; nt8++) {
            int cc = wn * 64 + nt8 * 8 + ccol;
            *reinterpret_cast<float2*>(out + (size_t)r * 256 + cc) =
                make_float2(C[mt][nt8][0], C[mt][nt8][1]);
            *reinterpret_cast<float2*>(out + (size_t)(r + 8) * 256 + cc) =
                make_float2(C[mt][nt8][2], C[mt][nt8][3]);
        }
    }
}

// ---- launch ---------------------------------------------------------------
extern "C" void kernel_launch(void* const* d_in, const int* in_sizes, int n_in,
                              void* d_out, int out_size) {
    const float* x       = (const float*)d_in[0];
    const float* baseW   = (const float*)d_in[1];
    const float* splineW = (const float*)d_in[2];
    float* out           = (float*)d_out;
    const int n_rows = in_sizes[0] / N_IN;            // 32768

    repack_kernel<<<(N_IN * KTOT + 255) / 256, 256>>>(baseW, splineW);

    cudaFuncSetAttribute(kan_hmma_kernel, cudaFuncAttributeMaxDynamicSharedMemorySize, DYN_SMEM);
    dim3 grid(n_rows / 64, 1);
    kan_hmma_kernel<<<grid, 256, DYN_SMEM>>>(x, out);
}

// round 7
// speedup vs baseline: 1.0001x; 1.0001x over previous
#include <cuda_runtime.h>
#include <cuda_fp16.h>
#include <stdint.h>

// out[32768,256] = A[32768, K=2304] * Wt[K,256], fp16 operands, fp32 accum,
// ldmatrix + mma.sync.m16n8k16 (portable for compute_100).
//
// K layout: k = 9*i + j; j=0: silu(x_i), j=1..8: cubic B-spline bases
// (closed-form, 4 nonzero, select-chain placement).
// CTA tile: 128 rows x 128 outs, grid (256, 2). 512 threads = 16 warps
// (4 per SMSP -> latency hiding; the r6 regression showed 8 warps starves).
// Chunk: 16 features = 144 k = 9 k16 steps, A gen'd on the fly, B cp.async,
// both double-buffered. SMEM rows: 304 B stride (76 words, 12 mod 32 ->
// ldmatrix and STS wavefronts bank-conflict-free).

#define N_IN   256
#define KTOT   2304
#define CHUNKS 16
#define CK     144
#define KSTEPS 9
#define ROWB   304
#define TBUF   (128 * ROWB)            // 38912
#define DYN_SMEM (4 * TBUF)            // A0 A1 B0 B1 = 155648

__device__ __align__(128) __half g_Wh[N_IN * KTOT];   // [out][k] fp16

// ---- helpers --------------------------------------------------------------
__device__ __forceinline__ uint32_t smem_u32(const void* p) {
    uint32_t a;
    asm("{ .reg .u64 t; cvta.to.shared.u64 t, %1; cvt.u32.u64 %0, t; }" : "=r"(a) : "l"(p));
    return a;
}
__device__ __forceinline__ void cp16(uint32_t dst, const void* src) {
    asm volatile("cp.async.cg.shared.global [%0], [%1], 16;" :: "r"(dst), "l"(src) : "memory");
}
__device__ __forceinline__ void cp_commit() {
    asm volatile("cp.async.commit_group;" ::: "memory");
}
template <int N>
__device__ __forceinline__ void cp_wait() {
    asm volatile("cp.async.wait_group %0;" :: "n"(N) : "memory");
}
__device__ __forceinline__ void ldm_x4(uint32_t& r0, uint32_t& r1, uint32_t& r2, uint32_t& r3,
                                       uint32_t addr) {
    asm volatile("ldmatrix.sync.aligned.m8n8.x4.shared.b16 {%0,%1,%2,%3}, [%4];"
                 : "=r"(r0), "=r"(r1), "=r"(r2), "=r"(r3) : "r"(addr));
}
__device__ __forceinline__ void mma16816(float& c0, float& c1, float& c2, float& c3,
                                         uint32_t a0, uint32_t a1, uint32_t a2, uint32_t a3,
                                         uint32_t b0, uint32_t b1) {
    asm volatile(
        "mma.sync.aligned.m16n8k16.row.col.f32.f16.f16.f32 "
        "{%0,%1,%2,%3}, {%4,%5,%6,%7}, {%8,%9}, {%0,%1,%2,%3};"
        : "+f"(c0), "+f"(c1), "+f"(c2), "+f"(c3)
        : "r"(a0), "r"(a1), "r"(a2), "r"(a3), "r"(b0), "r"(b1));
}

// ---- weight repack to fp16 [out][k] ---------------------------------------
__global__ void repack_kernel(const float* __restrict__ baseW,
                              const float* __restrict__ splineW) {
    int idx = blockIdx.x * blockDim.x + threadIdx.x;
    if (idx >= N_IN * KTOT) return;
    int o = idx / KTOT, k = idx % KTOT;
    int i = k / 9, j = k % 9;
    float v = (j == 0) ? baseW[o * N_IN + i] : splineW[o * (N_IN * 8) + i * 8 + (j - 1)];
    g_Wh[idx] = __float2half_rn(v);
}

// ---- main fused kernel ----------------------------------------------------
__global__ __launch_bounds__(512, 1)
void kan_hmma_kernel(const float* __restrict__ x, float* __restrict__ out) {
    extern __shared__ __align__(128) unsigned char dsm[];   // A0 A1 B0 B1
    const uint32_t sb = smem_u32(dsm);
    const int tid = threadIdx.x, wid = tid >> 5, lane = tid & 31;
    const int row0 = blockIdx.x * 128;
    const int ct   = blockIdx.y;                 // output col tile (0/1)

    // A generation: thread -> (row = tid&127, feature-quad fq = tid>>7)
    const int grow = tid & 127;
    const int fq   = tid >> 7;                   // 0..3 -> features fq*4..fq*4+3
    const float* xrow = x + (size_t)(row0 + grow) * N_IN;

    // warp tiling: 4 (m) x 4 (n); warp tile 32 rows x 32 cols
    const int wm = wid & 3;
    const int wn = wid >> 2;

    const uint32_t a_off = (uint32_t)(wm * 32 + (lane & 15)) * ROWB + ((lane >> 4) << 3) * 2;
    const uint32_t b_off = (uint32_t)(wn * 32 + ((lane >> 4) << 3) + (lane & 7)) * ROWB
                         + (((lane >> 3) & 1) << 3) * 2;

    float C[2][4][4];                            // [mt][n8][frag]
#pragma unroll
    for (int a = 0; a < 2; a++)
#pragma unroll
        for (int b = 0; b < 4; b++)
#pragma unroll
            for (int c = 0; c < 4; c++) C[a][b][c] = 0.f;

    // ---- A generator: silu + closed-form cubic B-spline window ----
    auto genA = [&](int c, uint32_t abyte) {
        float4 x4 = *reinterpret_cast<const float4*>(xrow + c * 16 + fq * 4);
        float xv[4] = {x4.x, x4.y, x4.z, x4.w};
        uint32_t pk[18];
#pragma unroll
        for (int ff = 0; ff < 4; ff++) {
            float v = xv[ff];
            float sil = v / (1.f + __expf(-v));
            int j0 = (int)floorf(fmaf(v, 2.5f, 5.5f));
            float g = fmaf(0.4f, (float)j0, -2.2f);
            float u = (v - g) * 2.5f;
            float u2 = u * u, u3 = u2 * u, omu = 1.f - u;
            float w0 = omu * omu * omu * (1.f / 6.f);
            float w1 = fmaf(0.5f, u3, fmaf(-1.f, u2, 2.f / 3.f));
            float w2 = fmaf(-0.5f, u3, fmaf(0.5f, u2, fmaf(0.5f, u, 1.f / 6.f)));
            float w3 = u3 * (1.f / 6.f);
            unsigned short h0 = __half_as_ushort(__float2half_rn(w0));
            unsigned short h1 = __half_as_ushort(__float2half_rn(w1));
            unsigned short h2 = __half_as_ushort(__float2half_rn(w2));
            unsigned short h3 = __half_as_ushort(__float2half_rn(w3));
            unsigned short hh[9];
            hh[0] = __half_as_ushort(__float2half_rn(sil));
#pragma unroll
            for (int i = 0; i < 8; i++) {
                int d = j0 - i;
                unsigned short b = (d == 0) ? h3 : (d == 1) ? h2
                                 : (d == 2) ? h1 : (d == 3) ? h0 : (unsigned short)0;
                hh[i + 1] = b;
            }
#pragma unroll
            for (int j = 0; j < 9; j++) {
                int pos = 9 * ff + j;
                uint32_t word = (uint32_t)hh[j] << ((pos & 1) * 16);
                if ((pos & 1) == 0) pk[pos >> 1] = word;
                else                pk[pos >> 1] |= word;
            }
        }
        unsigned char* dst = dsm + abyte + (uint32_t)grow * ROWB + (uint32_t)fq * 72;
#pragma unroll
        for (int q = 0; q < 9; q++)
            *reinterpret_cast<uint2*>(dst + q * 8) = make_uint2(pk[2 * q], pk[2 * q + 1]);
    };

    // ---- B stage via cp.async: 128 rows x 18 segs of 16B = 2304 segs ----
    auto issueB = [&](int c, uint32_t bbyte) {
        const __half* src0 = g_Wh + (size_t)(ct * 128) * KTOT + c * CK;
#pragma unroll
        for (int s = 0; s < 5; s++) {
            int e = tid + 512 * s;               // 0..2559, guard at 2304
            if (e < 2304) {
                int n = e / 18, seg = e % 18;
                cp16(sb + bbyte + (uint32_t)n * ROWB + seg * 16,
                     src0 + (size_t)n * KTOT + seg * 8);
            }
        }
        cp_commit();
    };

    // ---- prologue ----
    genA(0, 0);
    issueB(0, 2 * TBUF);
    issueB(1, 3 * TBUF);
    cp_wait<1>();
    __syncthreads();

    // ---- main loop ----
    for (int c = 0; c < CHUNKS; c++) {
        const int buf = c & 1;
        const uint32_t abase = sb + (uint32_t)buf * TBUF;
        const uint32_t bbase = sb + (uint32_t)(2 + buf) * TBUF;

#pragma unroll
        for (int s = 0; s < KSTEPS; s++) {
            const uint32_t kb = (uint32_t)(s * 16) * 2;
            uint32_t A[2][4], B[2][4];
#pragma unroll
            for (int mt = 0; mt < 2; mt++)
                ldm_x4(A[mt][0], A[mt][1], A[mt][2], A[mt][3],
                       abase + a_off + (uint32_t)mt * (16 * ROWB) + kb);
#pragma unroll
            for (int nt = 0; nt < 2; nt++)
                ldm_x4(B[nt][0], B[nt][1], B[nt][2], B[nt][3],
                       bbase + b_off + (uint32_t)nt * (16 * ROWB) + kb);
#pragma unroll
            for (int mt = 0; mt < 2; mt++)
#pragma unroll
                for (int nt = 0; nt < 2; nt++) {
                    mma16816(C[mt][2 * nt][0], C[mt][2 * nt][1],
                             C[mt][2 * nt][2], C[mt][2 * nt][3],
                             A[mt][0], A[mt][1], A[mt][2], A[mt][3],
                             B[nt][0], B[nt][1]);
                    mma16816(C[mt][2 * nt + 1][0], C[mt][2 * nt + 1][1],
                             C[mt][2 * nt + 1][2], C[mt][2 * nt + 1][3],
                             A[mt][0], A[mt][1], A[mt][2], A[mt][3],
                             B[nt][2], B[nt][3]);
                }
        }

        if (c + 1 < CHUNKS) genA(c + 1, (uint32_t)(buf ^ 1) * TBUF);
        __syncthreads();
        if (c + 2 < CHUNKS) {
            issueB(c + 2, (uint32_t)(2 + buf) * TBUF);
            cp_wait<1>();
        } else {
            cp_wait<0>();
        }
        __syncthreads();
    }

    // ---- epilogue: C frags -> gmem ----
    const int crow = lane >> 2, ccol = (lane & 3) * 2;
#pragma unroll
    for (int mt = 0; mt < 2; mt++) {
        int r = row0 + wm * 32 + mt * 16 + crow;
#pragma unroll
        for (int n8 = 0; n8 < 4; n8++) {
            int cc = ct * 128 + wn * 32 + n8 * 8 + ccol;
            *reinterpret_cast<float2*>(out + (size_t)r * 256 + cc) =
                make_float2(C[mt][n8][0], C[mt][n8][1]);
            *reinterpret_cast<float2*>(out + (size_t)(r + 8) * 256 + cc) =
                make_float2(C[mt][n8][2], C[mt][n8][3]);
        }
    }
}

// ---- launch ---------------------------------------------------------------
extern "C" void kernel_launch(void* const* d_in, const int* in_sizes, int n_in,
                              void* d_out, int out_size) {
    const float* x       = (const float*)d_in[0];
    const float* baseW   = (const float*)d_in[1];
    const float* splineW = (const float*)d_in[2];
    float* out           = (float*)d_out;
    const int n_rows = in_sizes[0] / N_IN;            // 32768

    repack_kernel<<<(N_IN * KTOT + 255) / 256, 256>>>(baseW, splineW);

    cudaFuncSetAttribute(kan_hmma_kernel, cudaFuncAttributeMaxDynamicSharedMemorySize, DYN_SMEM);
    dim3 grid(n_rows / 128, 2);
    kan_hmma_kernel<<<grid, 512, DYN_SMEM>>>(x, out);
}

// round 8
// speedup vs baseline: 1.1392x; 1.1391x over previous
#include <cuda_runtime.h>
#include <cuda_fp16.h>
#include <stdint.h>

// out[32768,256] = A[32768, K=2304] * Wt[K,256], fp16 operands, fp32 accum,
// ldmatrix + mma.sync.m16n8k16 (portable for compute_100).
//
// K layout: k = 9*i + j; j=0: silu(x_i), j=1..8: cubic B-spline bases
// (closed-form, 4 nonzero, select-chain placement).
//
// Occupancy-first design: CTA 64 rows x 128 outs, 256 threads, <=128 regs,
// 97KB smem -> 2 CTAs/SM so one CTA's compute covers the other's serial
// segments (genA, cp.async waits). A single-buffered, B double-buffered,
// x prefetched into registers one chunk ahead.
// Chunk: 16 features = 144 k = 9 k16 steps. 304-B smem row stride
// (76 words, 12 mod 32 -> ldmatrix/STS wavefronts conflict-free).

#define N_IN   256
#define KTOT   2304
#define CHUNKS 16
#define CK     144
#define KSTEPS 9
#define ROWB   304
#define ABUF   (64 * ROWB)             // 19456
#define BBUF   (128 * ROWB)            // 38912
#define DYN_SMEM (ABUF + 2 * BBUF)     // 97280 -> 2 CTAs/SM

__device__ __align__(128) __half g_Wh[N_IN * KTOT];   // [out][k] fp16

// ---- helpers --------------------------------------------------------------
__device__ __forceinline__ uint32_t smem_u32(const void* p) {
    uint32_t a;
    asm("{ .reg .u64 t; cvta.to.shared.u64 t, %1; cvt.u32.u64 %0, t; }" : "=r"(a) : "l"(p));
    return a;
}
__device__ __forceinline__ void cp16(uint32_t dst, const void* src) {
    asm volatile("cp.async.cg.shared.global [%0], [%1], 16;" :: "r"(dst), "l"(src) : "memory");
}
__device__ __forceinline__ void cp_commit() {
    asm volatile("cp.async.commit_group;" ::: "memory");
}
template <int N>
__device__ __forceinline__ void cp_wait() {
    asm volatile("cp.async.wait_group %0;" :: "n"(N) : "memory");
}
__device__ __forceinline__ void ldm_x4(uint32_t& r0, uint32_t& r1, uint32_t& r2, uint32_t& r3,
                                       uint32_t addr) {
    asm volatile("ldmatrix.sync.aligned.m8n8.x4.shared.b16 {%0,%1,%2,%3}, [%4];"
                 : "=r"(r0), "=r"(r1), "=r"(r2), "=r"(r3) : "r"(addr));
}
__device__ __forceinline__ void mma16816(float& c0, float& c1, float& c2, float& c3,
                                         uint32_t a0, uint32_t a1, uint32_t a2, uint32_t a3,
                                         uint32_t b0, uint32_t b1) {
    asm volatile(
        "mma.sync.aligned.m16n8k16.row.col.f32.f16.f16.f32 "
        "{%0,%1,%2,%3}, {%4,%5,%6,%7}, {%8,%9}, {%0,%1,%2,%3};"
        : "+f"(c0), "+f"(c1), "+f"(c2), "+f"(c3)
        : "r"(a0), "r"(a1), "r"(a2), "r"(a3), "r"(b0), "r"(b1));
}

// ---- weight repack to fp16 [out][k] ---------------------------------------
__global__ void repack_kernel(const float* __restrict__ baseW,
                              const float* __restrict__ splineW) {
    int idx = blockIdx.x * blockDim.x + threadIdx.x;
    if (idx >= N_IN * KTOT) return;
    int o = idx / KTOT, k = idx % KTOT;
    int i = k / 9, j = k % 9;
    float v = (j == 0) ? baseW[o * N_IN + i] : splineW[o * (N_IN * 8) + i * 8 + (j - 1)];
    g_Wh[idx] = __float2half_rn(v);
}

// ---- main fused kernel ----------------------------------------------------
__global__ __launch_bounds__(256, 2)
void kan_hmma_kernel(const float* __restrict__ x, float* __restrict__ out) {
    extern __shared__ __align__(128) unsigned char dsm[];   // A | B0 | B1
    const uint32_t sb = smem_u32(dsm);
    const int tid = threadIdx.x, wid = tid >> 5, lane = tid & 31;
    const int row0 = blockIdx.x * 64;
    const int ct   = blockIdx.y;                 // output col tile (0/1)

    // A generation: thread -> (row = tid&63, feature-quad fq = tid>>6)
    const int grow = tid & 63;
    const int fq   = tid >> 6;                   // 0..3 -> features fq*4..+3
    const float* xrow = x + (size_t)(row0 + grow) * N_IN;

    // warp tiling: 2 (m) x 4 (n); warp tile 32 rows x 32 cols
    const int wm = wid & 1;
    const int wn = wid >> 1;

    const uint32_t a_off = (uint32_t)(wm * 32 + (lane & 15)) * ROWB + ((lane >> 4) << 3) * 2;
    const uint32_t b_off = (uint32_t)(wn * 32 + ((lane >> 4) << 3) + (lane & 7)) * ROWB
                         + (((lane >> 3) & 1) << 3) * 2;

    float C[2][4][4];                            // [mt][n8][frag]
#pragma unroll
    for (int a = 0; a < 2; a++)
#pragma unroll
        for (int b = 0; b < 4; b++)
#pragma unroll
            for (int c = 0; c < 4; c++) C[a][b][c] = 0.f;

    // ---- A generator from pre-loaded x quad ----
    auto genA = [&](float4 x4) {
        float xv[4] = {x4.x, x4.y, x4.z, x4.w};
        uint32_t pk[18];
#pragma unroll
        for (int ff = 0; ff < 4; ff++) {
            float v = xv[ff];
            float sil = v / (1.f + __expf(-v));
            int j0 = (int)floorf(fmaf(v, 2.5f, 5.5f));
            float g = fmaf(0.4f, (float)j0, -2.2f);
            float u = (v - g) * 2.5f;
            float u2 = u * u, u3 = u2 * u, omu = 1.f - u;
            float w0 = omu * omu * omu * (1.f / 6.f);
            float w1 = fmaf(0.5f, u3, fmaf(-1.f, u2, 2.f / 3.f));
            float w2 = fmaf(-0.5f, u3, fmaf(0.5f, u2, fmaf(0.5f, u, 1.f / 6.f)));
            float w3 = u3 * (1.f / 6.f);
            unsigned short h0 = __half_as_ushort(__float2half_rn(w0));
            unsigned short h1 = __half_as_ushort(__float2half_rn(w1));
            unsigned short h2 = __half_as_ushort(__float2half_rn(w2));
            unsigned short h3 = __half_as_ushort(__float2half_rn(w3));
            unsigned short hh[9];
            hh[0] = __half_as_ushort(__float2half_rn(sil));
#pragma unroll
            for (int i = 0; i < 8; i++) {
                int d = j0 - i;
                unsigned short b = (d == 0) ? h3 : (d == 1) ? h2
                                 : (d == 2) ? h1 : (d == 3) ? h0 : (unsigned short)0;
                hh[i + 1] = b;
            }
#pragma unroll
            for (int j = 0; j < 9; j++) {
                int pos = 9 * ff + j;
                uint32_t word = (uint32_t)hh[j] << ((pos & 1) * 16);
                if ((pos & 1) == 0) pk[pos >> 1] = word;
                else                pk[pos >> 1] |= word;
            }
        }
        unsigned char* dst = dsm + (uint32_t)grow * ROWB + (uint32_t)fq * 72;
#pragma unroll
        for (int q = 0; q < 9; q++)
            *reinterpret_cast<uint2*>(dst + q * 8) = make_uint2(pk[2 * q], pk[2 * q + 1]);
    };

    // ---- B stage via cp.async: 128 rows x 18 segs of 16B = 2304 segs ----
    auto issueB = [&](int c, uint32_t bbyte) {
        const __half* src0 = g_Wh + (size_t)(ct * 128) * KTOT + c * CK;
#pragma unroll
        for (int s = 0; s < 9; s++) {
            int e = tid + 256 * s;               // 0..2303
            int n = e / 18, seg = e % 18;
            cp16(sb + bbyte + (uint32_t)n * ROWB + seg * 16,
                 src0 + (size_t)n * KTOT + seg * 8);
        }
        cp_commit();
    };

    // ---- prologue ----
    issueB(0, ABUF);
    issueB(1, ABUF + BBUF);
    genA(*reinterpret_cast<const float4*>(xrow + fq * 4));
    cp_wait<1>();
    __syncthreads();

    // ---- main loop ----
    for (int c = 0; c < CHUNKS; c++) {
        const int buf = c & 1;
        const uint32_t bbase = sb + ABUF + (uint32_t)buf * BBUF;

        float4 xn;
        if (c + 1 < CHUNKS)
            xn = *reinterpret_cast<const float4*>(xrow + (c + 1) * 16 + fq * 4);

#pragma unroll
        for (int s = 0; s < KSTEPS; s++) {
            const uint32_t kb = (uint32_t)(s * 16) * 2;
            uint32_t A[2][4], B[2][4];
#pragma unroll
            for (int mt = 0; mt < 2; mt++)
                ldm_x4(A[mt][0], A[mt][1], A[mt][2], A[mt][3],
                       sb + a_off + (uint32_t)mt * (16 * ROWB) + kb);
#pragma unroll
            for (int nt = 0; nt < 2; nt++)
                ldm_x4(B[nt][0], B[nt][1], B[nt][2], B[nt][3],
                       bbase + b_off + (uint32_t)nt * (16 * ROWB) + kb);
#pragma unroll
            for (int mt = 0; mt < 2; mt++)
#pragma unroll
                for (int nt = 0; nt < 2; nt++) {
                    mma16816(C[mt][2 * nt][0], C[mt][2 * nt][1],
                             C[mt][2 * nt][2], C[mt][2 * nt][3],
                             A[mt][0], A[mt][1], A[mt][2], A[mt][3],
                             B[nt][0], B[nt][1]);
                    mma16816(C[mt][2 * nt + 1][0], C[mt][2 * nt + 1][1],
                             C[mt][2 * nt + 1][2], C[mt][2 * nt + 1][3],
                             A[mt][0], A[mt][1], A[mt][2], A[mt][3],
                             B[nt][2], B[nt][3]);
                }
        }

        __syncthreads();                          // all reads of A and B[buf] done
        if (c + 1 < CHUNKS) {
            if (c + 2 < CHUNKS) issueB(c + 2, ABUF + (uint32_t)buf * BBUF);
            genA(xn);                             // overwrite single A buffer
            if (c + 2 < CHUNKS) cp_wait<1>();
            else                cp_wait<0>();
            __syncthreads();                      // A(c+1) + B(c+1) ready
        }
    }

    // ---- epilogue: C frags -> gmem ----
    const int crow = lane >> 2, ccol = (lane & 3) * 2;
#pragma unroll
    for (int mt = 0; mt < 2; mt++) {
        int r = row0 + wm * 32 + mt * 16 + crow;
#pragma unroll
        for (int n8 = 0; n8 < 4; n8++) {
            int cc = ct * 128 + wn * 32 + n8 * 8 + ccol;
            *reinterpret_cast<float2*>(out + (size_t)r * 256 + cc) =
                make_float2(C[mt][n8][0], C[mt][n8][1]);
            *reinterpret_cast<float2*>(out + (size_t)(r + 8) * 256 + cc) =
                make_float2(C[mt][n8][2], C[mt][n8][3]);
        }
    }
}

// ---- launch ---------------------------------------------------------------
extern "C" void kernel_launch(void* const* d_in, const int* in_sizes, int n_in,
                              void* d_out, int out_size) {
    const float* x       = (const float*)d_in[0];
    const float* baseW   = (const float*)d_in[1];
    const float* splineW = (const float*)d_in[2];
    float* out           = (float*)d_out;
    const int n_rows = in_sizes[0] / N_IN;            // 32768

    repack_kernel<<<(N_IN * KTOT + 255) / 256, 256>>>(baseW, splineW);

    cudaFuncSetAttribute(kan_hmma_kernel, cudaFuncAttributeMaxDynamicSharedMemorySize, DYN_SMEM);
    dim3 grid(n_rows / 64, 2);
    kan_hmma_kernel<<<grid, 256, DYN_SMEM>>>(x, out);
}